// round 16
// baseline (speedup 1.0000x reference)
#include <cuda_runtime.h>
#include <cuda_fp16.h>
#include <mma.h>
#include <cstdint>
#include <math.h>

using namespace nvcuda;

#define Hdim 1024
#define INdim 512
#define Bdim 256
#define Tdim 256
#define HB (Hdim * Bdim)          // 262144 elements
#define KSPLIT 2
#define XT_STRIDE (INdim * Bdim)
#define NBLOCKS 128
#define KCHUNK 32

// recurrence smem: persistent A slice 128x512 + FULL B slice 512x64 halfs
// + v-transpose tile (8 x 257 floats)
#define A_LDR 520                 // 512 + 8 pad halfs
#define SA_R (128 * A_LDR)        // 66560 halfs = 133120 B
#define B_LDR 72                  // 64 + 8 pad halfs
#define SB_R (512 * B_LDR)        // 36864 halfs = 73728 B
#define VT_LD 257
#define VT_BYTES (8 * VT_LD * 4)  // 8224 B
#define SMEM_REC ((SA_R + SB_R) * 2 + VT_BYTES)  // 215072 B

// proj smem: pipeline (A 128x32, B 32x128, x2) OR fp32->fp16 epilogue stage
#define A_LDP 40
#define B_LDP 136
#define SA_P (128 * A_LDP)
#define SB_P (KCHUNK * B_LDP)
#define SMEM_PROJ_PIPE (2 * (SA_P + SB_P) * 2)   // 37888 B
#define C_LDP 132
#define SMEM_PROJ (128 * C_LDP * 4)              // 67584 B (> pipe) -> 2/SM

// ---------------- device scratch (no cudaMalloc allowed) ----------------
// ONLY referenced in device code (host-arg binding of __device__ globals
// silently resolves to the host shadow on GB300 ATS — the R4/R5 bug).
__device__ __align__(1024) __half g_Azh[(size_t)Tdim * HB];  // 128 MiB fp16
__device__ __align__(1024) __half g_Arh[(size_t)Tdim * HB];  // 128 MiB fp16
__device__ __align__(1024) __half g_xh[(size_t)Tdim * XT_STRIDE];  // 64 MiB
__device__ __align__(1024) __half g_Kh[Hdim * Hdim];
__device__ __align__(1024) __half g_Wh[Hdim * Hdim];
__device__ __align__(1024) __half g_Pzh[Hdim * INdim];
__device__ __align__(1024) __half g_Prh[Hdim * INdim];
__device__ __align__(1024) __half g_rh[HB];
__device__ __align__(1024) __half g_mh[HB];
__device__ __align__(1024) float g_G1p[KSPLIT * HB];
__device__ __align__(1024) float g_G2p[KSPLIT * HB];
__device__ unsigned long long g_barrier;  // monotonic, never reset

// ---------------- helpers ----------------
__device__ __forceinline__ float sigm(float x) {
    return 1.0f / (1.0f + __expf(-x));
}
__device__ __forceinline__ uint32_t s2u(const void* p) {
    return (uint32_t)__cvta_generic_to_shared(p);
}
__device__ __forceinline__ void cp_async16_ca(uint32_t saddr, const void* g) {
    asm volatile("cp.async.ca.shared.global [%0], [%1], 16;"
                 :: "r"(saddr), "l"(g));
}
__device__ __forceinline__ void cp_async16_cg(uint32_t saddr, const void* g) {
    asm volatile("cp.async.cg.shared.global [%0], [%1], 16;"
                 :: "r"(saddr), "l"(g));
}
__device__ __forceinline__ void cp_commit() {
    asm volatile("cp.async.commit_group;" ::: "memory");
}
template <int N>
__device__ __forceinline__ void cp_wait() {
    asm volatile("cp.async.wait_group %0;" :: "n"(N) : "memory");
}

// Flat grid barrier (proven R11): monotonic counter, release-RMW arrive,
// acquire-load poll.
__device__ __forceinline__ void grid_sync() {
    __syncthreads();
    if (threadIdx.x == 0) {
        unsigned long long old;
        asm volatile("atom.release.gpu.global.add.u64 %0, [%1], 1;"
                     : "=l"(old) : "l"(&g_barrier) : "memory");
        const unsigned long long target = (old / NBLOCKS + 1) * NBLOCKS;
        unsigned long long cur;
        do {
            asm volatile("ld.acquire.gpu.global.u64 %0, [%1];"
                         : "=l"(cur) : "l"(&g_barrier) : "memory");
        } while (cur < target);
    }
    __syncthreads();
}

// ---------------- weight conversion: fp32 -> fp16 (one launch) -----------
__global__ __launch_bounds__(256) void conv_weights(
    const float* __restrict__ Km, const float* __restrict__ Wr,
    const float* __restrict__ Pz, const float* __restrict__ Pr)
{
    const size_t i = ((size_t)blockIdx.x * 256 + threadIdx.x) * 4;
    const float* src;
    __half* dst;
    size_t off;
    if (i < (size_t)Hdim * Hdim) { src = Km; dst = g_Kh; off = i; }
    else if (i < 2ull * Hdim * Hdim) {
        src = Wr; dst = g_Wh; off = i - (size_t)Hdim * Hdim;
    } else if (i < 2ull * Hdim * Hdim + (size_t)Hdim * INdim) {
        src = Pz; dst = g_Pzh; off = i - 2ull * Hdim * Hdim;
    } else {
        src = Pr; dst = g_Prh; off = i - 2ull * Hdim * Hdim - (size_t)Hdim * INdim;
    }
    float4 v = *(const float4*)&src[off];
    __half h[4] = { __float2half_rn(v.x), __float2half_rn(v.y),
                    __float2half_rn(v.z), __float2half_rn(v.w) };
    *(uint2*)&dst[off] = *(uint2*)h;
}

__global__ __launch_bounds__(256) void conv_x(const float* __restrict__ x) {
    const size_t i = ((size_t)blockIdx.x * 256 + threadIdx.x) * 4;
    float4 v = *(const float4*)&x[i];
    __half h[4] = { __float2half_rn(v.x), __float2half_rn(v.y),
                    __float2half_rn(v.z), __float2half_rn(v.w) };
    *(uint2*)&g_xh[i] = *(uint2*)h;
}

// ---------------- projection GEMM: Az/Ar[t] = P @ x_t (fp16 output) ------
// Block tile 128x128, warp tile 32x64 (4x2 warps). grid (8, 2, 2*Tdim).
// Epilogue stages fp32 acc through smem, converts to fp16 global.
__global__ __launch_bounds__(256, 2) void proj_gemm() {
    extern __shared__ __half smh[];
    const int tid = threadIdx.x;
    const int warp = tid >> 5;
    const int wm = warp >> 1, wn = warp & 1;
    const int which = blockIdx.z & 1, q = blockIdx.z >> 1;
    const __half* A = which ? g_Prh : g_Pzh;
    const __half* B = g_xh + (size_t)q * XT_STRIDE;
    __half* C = (which ? g_Arh : g_Azh) + (size_t)q * HB;
    const int m0 = blockIdx.x * 128, n0 = blockIdx.y * 128;

    __half* const sA[2] = { smh, smh + SA_P };
    __half* const sB[2] = { smh + 2 * SA_P, smh + 2 * SA_P + SB_P };
    const uint32_t aB[2] = { s2u(sA[0]), s2u(sA[1]) };
    const uint32_t bB[2] = { s2u(sB[0]), s2u(sB[1]) };

    auto issue = [&](int c, int s) {
        const int kc = c * KCHUNK;
#pragma unroll
        for (int i = 0; i < 2; ++i) {
            const int e = i * 256 + tid, r = e >> 2, f8 = e & 3;
            cp_async16_ca(aB[s] + (uint32_t)(r * A_LDP + f8 * 8) * 2,
                          A + (size_t)(m0 + r) * INdim + kc + f8 * 8);
        }
#pragma unroll
        for (int i = 0; i < 2; ++i) {
            const int e = i * 256 + tid, r = e >> 4, f8 = e & 15;
            cp_async16_ca(bB[s] + (uint32_t)(r * B_LDP + f8 * 8) * 2,
                          B + (size_t)(kc + r) * Bdim + n0 + f8 * 8);
        }
        cp_commit();
    };

    wmma::fragment<wmma::accumulator, 16, 16, 16, float> acc[2][4];
#pragma unroll
    for (int i = 0; i < 2; ++i)
#pragma unroll
        for (int j = 0; j < 4; ++j) wmma::fill_fragment(acc[i][j], 0.0f);

    const int nChunks = INdim / KCHUNK;  // 16
    issue(0, 0);
    for (int c = 0; c < nChunks; ++c) {
        if (c + 1 < nChunks) { issue(c + 1, (c + 1) & 1); cp_wait<1>(); }
        else                 { cp_wait<0>(); }
        __syncthreads();
        const __half* cA = sA[c & 1];
        const __half* cB = sB[c & 1];
#pragma unroll
        for (int ks = 0; ks < 2; ++ks) {
            wmma::fragment<wmma::matrix_a, 16, 16, 16, __half,
                           wmma::row_major> af[2];
            wmma::fragment<wmma::matrix_b, 16, 16, 16, __half,
                           wmma::row_major> bf[4];
#pragma unroll
            for (int i = 0; i < 2; ++i)
                wmma::load_matrix_sync(af[i],
                    cA + (wm * 32 + i * 16) * A_LDP + ks * 16, A_LDP);
#pragma unroll
            for (int j = 0; j < 4; ++j)
                wmma::load_matrix_sync(bf[j],
                    cB + (ks * 16) * B_LDP + wn * 64 + j * 16, B_LDP);
#pragma unroll
            for (int i = 0; i < 2; ++i)
#pragma unroll
                for (int j = 0; j < 4; ++j)
                    wmma::mma_sync(acc[i][j], af[i], bf[j], acc[i][j]);
        }
        __syncthreads();
    }

    // epilogue: stage fp32 acc in smem (aliases pipeline), convert to fp16
    float* sC = (float*)smh;
#pragma unroll
    for (int i = 0; i < 2; ++i)
#pragma unroll
        for (int j = 0; j < 4; ++j)
            wmma::store_matrix_sync(
                sC + (wm * 32 + i * 16) * C_LDP + wn * 64 + j * 16,
                acc[i][j], C_LDP, wmma::mem_row_major);
    __syncthreads();
    {
        const int r = tid >> 1, cs = (tid & 1) * 64;
        const float* src = sC + r * C_LDP + cs;
        __half* dst = C + (size_t)(m0 + r) * Bdim + n0 + cs;
#pragma unroll
        for (int g = 0; g < 8; ++g) {
            float4 a = *(const float4*)&src[g * 8];
            float4 b = *(const float4*)&src[g * 8 + 4];
            __half h8[8] = { __float2half_rn(a.x), __float2half_rn(a.y),
                             __float2half_rn(a.z), __float2half_rn(a.w),
                             __float2half_rn(b.x), __float2half_rn(b.y),
                             __float2half_rn(b.z), __float2half_rn(b.w) };
            *(uint4*)&dst[g * 8] = *(uint4*)h8;
        }
    }
}

// ---------------- persistent recurrence kernel ---------------------------
// 128 blocks x 256 threads, 1 block/SM (215KB smem). R11 structure; elem
// writes OUTPUT DIRECTLY (transposed via 8KB smem tile) — no v staging, no
// transpose kernel. Az/Ar read as fp16.
__global__ __launch_bounds__(256, 1) void recurrence(
    const float* __restrict__ c_x, const float* __restrict__ c_u,
    const float* __restrict__ c_U, const float* __restrict__ gz,
    const float* __restrict__ br, float* __restrict__ out)
{
    extern __shared__ __half smh[];
    const int tid = threadIdx.x;
    const int bid = blockIdx.x;

    // ----- elem identity: 8 consecutive elements of [H][B] -----
    const int idx = (bid * 256 + tid) * 8;
    const int h = idx >> 8;                  // h = bid*8 + (tid>>5)
    const float zx = 0.001f + 0.099f * sigm(c_x[h]);
    const float zu = 0.001f + 0.099f * sigm(c_u[h]);
    const float Uc = 0.9f * sigm(c_U[h]);
    const float gzh = gz[h], brh = br[h];
    float v[8], X[8], U[8];
#pragma unroll
    for (int e = 0; e < 8; ++e) { v[e] = 0.f; X[e] = 1.f; U[e] = 0.9f; }

    // ----- gemm identity: 128 blocks = mb8 x nb4 x which2 x q2 -----
    const int which = bid & 1;
    const int q = (bid >> 1) & 1;
    const int nb = (bid >> 2) & 3;
    const int mb = bid >> 4;
    const int warp = tid >> 5;
    const int wm = warp >> 1, wn = warp & 1;
    const __half* Ag = which ? g_Wh : g_Kh;
    const __half* Bg = which ? g_mh : g_rh;
    float* Cg = (which ? g_G2p : g_G1p) + (size_t)q * HB;
    const int kStart = q * (Hdim / KSPLIT);   // 0 or 512
    const int m0 = mb * 128, n0 = nb * 64;

    __half* const sA = smh;               // persistent 128 x A_LDR
    __half* const sB = smh + SA_R;        // full 512 x B_LDR
    float* const vt = (float*)(smh + SA_R + SB_R);  // 8 x VT_LD floats
    const uint32_t aBase = s2u(sA);
    const uint32_t bBase = s2u(sB);

    // ----- one-time A-slice load -----
    {
        const __half* Asrc = Ag + (size_t)m0 * Hdim + kStart;
#pragma unroll
        for (int i = 0; i < 32; ++i) {
            const int e = i * 256 + tid, r = e >> 6, g = e & 63;
            cp_async16_ca(aBase + (uint32_t)(r * A_LDR + g * 8) * 2,
                          Asrc + (size_t)r * Hdim + g * 8);
        }
        cp_commit();
        cp_wait<0>();
        __syncthreads();
    }

    // per-chunk B load: 32 rows x 8 granules = 256 cp.async (1/thread)
    const int brow = tid >> 3, bg8 = tid & 7;
    auto issueB = [&](int c) {
        const int kc = kStart + c * KCHUNK;
        cp_async16_cg(
            bBase + (uint32_t)((c * KCHUNK + brow) * B_LDR + bg8 * 8) * 2,
            Bg + (size_t)(kc + brow) * Bdim + n0 + bg8 * 8);
    };

    // ----- initial elem (t = 0): v=0 -> r, m -----
    {
        __half rr[8], mm[8];
#pragma unroll
        for (int e = 0; e < 8; ++e) {
            const float r = sigm(v[e]);
            float Xn = zx + (1.0f - zx) * X[e] - U[e] * X[e] * r;
            float Un = Uc * zu + (1.0f - zu) * U[e] + Uc * (1.0f - U[e]) * r;
            Un = fminf(fmaxf(Un, Uc), 1.0f);
            X[e] = Xn;
            U[e] = Un;
            rr[e] = __float2half_rn(r);
            mm[e] = __float2half_rn(Un * Xn * r);
        }
        *(uint4*)&g_rh[idx] = *(uint4*)rr;
        *(uint4*)&g_mh[idx] = *(uint4*)mm;
    }
    grid_sync();

    for (int t = 0; t < Tdim; ++t) {
        // ===== gemm phase: C_q = A_slice @ B[kStart:+512, n0:+64] =====
        float az[8], ar[8];
        {
#pragma unroll
            for (int c = 0; c < 4; ++c) issueB(c);
            cp_commit();
#pragma unroll
            for (int c = 4; c < 16; ++c) issueB(c);
            cp_commit();

            wmma::fragment<wmma::accumulator, 16, 16, 16, float> acc[2][2];
#pragma unroll
            for (int i = 0; i < 2; ++i)
#pragma unroll
                for (int j = 0; j < 2; ++j) wmma::fill_fragment(acc[i][j], 0.0f);

            cp_wait<1>();
            __syncthreads();
#pragma unroll 2
            for (int c = 0; c < 4; ++c) {
#pragma unroll
                for (int ks = 0; ks < 2; ++ks) {
                    wmma::fragment<wmma::matrix_a, 16, 16, 16, __half,
                                   wmma::row_major> af[2];
                    wmma::fragment<wmma::matrix_b, 16, 16, 16, __half,
                                   wmma::row_major> bf[2];
#pragma unroll
                    for (int i = 0; i < 2; ++i)
                        wmma::load_matrix_sync(af[i],
                            sA + (wm * 32 + i * 16) * A_LDR + c * 32 + ks * 16,
                            A_LDR);
#pragma unroll
                    for (int j = 0; j < 2; ++j)
                        wmma::load_matrix_sync(bf[j],
                            sB + (c * 32 + ks * 16) * B_LDR + wn * 32 + j * 16,
                            B_LDR);
#pragma unroll
                    for (int i = 0; i < 2; ++i)
#pragma unroll
                        for (int j = 0; j < 2; ++j)
                            wmma::mma_sync(acc[i][j], af[i], bf[j], acc[i][j]);
                }
            }
            cp_wait<0>();
            __syncthreads();
#pragma unroll 2
            for (int c = 4; c < 16; ++c) {
#pragma unroll
                for (int ks = 0; ks < 2; ++ks) {
                    wmma::fragment<wmma::matrix_a, 16, 16, 16, __half,
                                   wmma::row_major> af[2];
                    wmma::fragment<wmma::matrix_b, 16, 16, 16, __half,
                                   wmma::row_major> bf[2];
#pragma unroll
                    for (int i = 0; i < 2; ++i)
                        wmma::load_matrix_sync(af[i],
                            sA + (wm * 32 + i * 16) * A_LDR + c * 32 + ks * 16,
                            A_LDR);
#pragma unroll
                    for (int j = 0; j < 2; ++j)
                        wmma::load_matrix_sync(bf[j],
                            sB + (c * 32 + ks * 16) * B_LDR + wn * 32 + j * 16,
                            B_LDR);
#pragma unroll
                    for (int i = 0; i < 2; ++i)
#pragma unroll
                        for (int j = 0; j < 2; ++j)
                            wmma::mma_sync(acc[i][j], af[i], bf[j], acc[i][j]);
                }
            }
            const int row = m0 + wm * 32, col = n0 + wn * 32;
#pragma unroll
            for (int i = 0; i < 2; ++i)
#pragma unroll
                for (int j = 0; j < 2; ++j)
                    wmma::store_matrix_sync(
                        Cg + (size_t)(row + i * 16) * Bdim + col + j * 16,
                        acc[i][j], Bdim, wmma::mem_row_major);

            // prefetch this step's Az/Ar (fp16, barrier-independent)
            const size_t off = (size_t)t * HB + idx;
            uint4 azu = *(const uint4*)&g_Azh[off];
            uint4 aru = *(const uint4*)&g_Arh[off];
            const __half2* azp = (const __half2*)&azu;
            const __half2* arp = (const __half2*)&aru;
#pragma unroll
            for (int p = 0; p < 4; ++p) {
                float2 fa = __half22float2(azp[p]);
                float2 fb = __half22float2(arp[p]);
                az[p * 2] = fa.x;  az[p * 2 + 1] = fa.y;
                ar[p * 2] = fb.x;  ar[p * 2 + 1] = fb.y;
            }
        }
        grid_sync();

        // ===== elem phase =====
        {
            float s1[8], s2[8], tmp[4];
#pragma unroll
            for (int g = 0; g < 2; ++g) {
                *(float4*)&s1[g * 4] = __ldcg((const float4*)&g_G1p[idx + g * 4]);
                *(float4*)&s2[g * 4] = __ldcg((const float4*)&g_G2p[idx + g * 4]);
                *(float4*)tmp = __ldcg((const float4*)&g_G1p[HB + idx + g * 4]);
#pragma unroll
                for (int e = 0; e < 4; ++e) s1[g * 4 + e] += tmp[e];
                *(float4*)tmp = __ldcg((const float4*)&g_G2p[HB + idx + g * 4]);
#pragma unroll
                for (int e = 0; e < 4; ++e) s2[g * 4 + e] += tmp[e];
            }
#pragma unroll
            for (int e = 0; e < 8; ++e) {
                float zt = 0.1f * sigm(s1[e] + az[e] + gzh);
                v[e] = (1.0f - zt) * v[e] + 0.1f * (s2[e] + ar[e] + brh);
            }

            // publish r/m (the only cross-block data)
            if (t + 1 < Tdim) {
                __half rr[8], mm[8];
#pragma unroll
                for (int e = 0; e < 8; ++e) {
                    const float r = sigm(v[e]);
                    float Xn = zx + (1.0f - zx) * X[e] - U[e] * X[e] * r;
                    float Un = Uc * zu + (1.0f - zu) * U[e] +
                               Uc * (1.0f - U[e]) * r;
                    Un = fminf(fmaxf(Un, Uc), 1.0f);
                    X[e] = Xn;
                    U[e] = Un;
                    rr[e] = __float2half_rn(r);
                    mm[e] = __float2half_rn(Un * Xn * r);
                }
                *(uint4*)&g_rh[idx] = *(uint4*)rr;
                *(uint4*)&g_mh[idx] = *(uint4*)mm;
            }

            // direct transposed output: stage v in smem tile, write
            // out[t][b][h0:h0+8] with coalesced 32B stores.
            {
                const int hh = tid >> 5;            // 0..7 (row within tile)
                const int b0 = (tid & 31) * 8;      // col base
#pragma unroll
                for (int e = 0; e < 8; ++e) vt[hh * VT_LD + b0 + e] = v[e];
                __syncthreads();
                float o8[8];
#pragma unroll
                for (int r = 0; r < 8; ++r) o8[r] = vt[r * VT_LD + tid];
                float* dst = out + (size_t)t * HB + (size_t)tid * Hdim + bid * 8;
                __stcs((float4*)dst, *(float4*)&o8[0]);
                __stcs((float4*)(dst + 4), *(float4*)&o8[4]);
            }
        }
        if (t + 1 < Tdim) grid_sync();
    }
}

// ---------------- launch ----------------
extern "C" void kernel_launch(void* const* d_in, const int* in_sizes, int n_in,
                              void* d_out, int out_size)
{
    const float* x   = (const float*)d_in[0];  // (T, IN, B)
    const float* c_x = (const float*)d_in[1];
    const float* c_u = (const float*)d_in[2];
    const float* c_U = (const float*)d_in[3];
    const float* w_r = (const float*)d_in[4];  // (H,H)
    const float* p_r = (const float*)d_in[5];  // (H,IN)
    const float* b_r = (const float*)d_in[6];
    const float* g_z = (const float*)d_in[7];
    const float* Km  = (const float*)d_in[8];  // (H,H)
    const float* p_z = (const float*)d_in[9];  // (H,IN)
    float* out = (float*)d_out;                // (T, B, H)

    cudaFuncSetAttribute(proj_gemm,
                         cudaFuncAttributeMaxDynamicSharedMemorySize, SMEM_PROJ);
    cudaFuncSetAttribute(recurrence,
                         cudaFuncAttributeMaxDynamicSharedMemorySize, SMEM_REC);

    conv_weights<<<(2 * Hdim * Hdim + 2 * Hdim * INdim) / 1024, 256>>>(
        Km, w_r, p_z, p_r);
    conv_x<<<(int)(((size_t)Tdim * XT_STRIDE) / 1024), 256>>>(x);
    proj_gemm<<<dim3(8, 2, 2 * Tdim), 256, SMEM_PROJ>>>();
    recurrence<<<NBLOCKS, 256, SMEM_REC>>>(c_x, c_u, c_U, g_z, b_r, out);
}